// round 13
// baseline (speedup 1.0000x reference)
#include <cuda_runtime.h>
#include <cuda_fp16.h>
#include <math.h>
#include <stdint.h>

// Problem constants
#define B 8
#define NTOK 1024
#define E 768
#define H 8
#define D 96
#define BHM (B * H)
#define MROWS (B * NTOK)

// ---------------- device scratch (no allocations allowed) ----------------
__device__ __half g_Xm[MROWS * E];
__device__ __half g_Xp[MROWS * E];
__device__ __half g_Wq[E * E];
__device__ __half g_Wk[E * E];
__device__ __half g_Wv[E * E];
__device__ __half g_Wo[E * E];
__device__ __half g_Q[B * H * NTOK * D];
__device__ __half g_K[B * H * NTOK * D];
__device__ __half g_V[B * H * NTOK * D];
__device__ __half g_S[(size_t)BHM * NTOK * NTOK];
__device__ __half g_A[B * NTOK * E];

// ---------------------------------------------------------------------------
__device__ __forceinline__ uint32_t pack_half2(__half lo, __half hi) {
    __half2 h = __halves2half2(lo, hi);
    return *reinterpret_cast<uint32_t*>(&h);
}

__device__ __forceinline__ uint32_t smem_u32(const void* p) {
    uint32_t a;
    asm("{ .reg .u64 t; cvta.to.shared.u64 t, %1; cvt.u32.u64 %0, t; }"
        : "=r"(a) : "l"(p));
    return a;
}

__device__ __forceinline__ void cp_async16(uint32_t smem_addr, const void* gptr) {
    asm volatile("cp.async.cg.shared.global [%0], [%1], 16;"
                 :: "r"(smem_addr), "l"(gptr));
}
__device__ __forceinline__ void cp_commit() {
    asm volatile("cp.async.commit_group;");
}
template <int N>
__device__ __forceinline__ void cp_wait() {
    asm volatile("cp.async.wait_group %0;" :: "n"(N));
}

__device__ __forceinline__ void ldsm_x4(uint32_t& r0, uint32_t& r1, uint32_t& r2, uint32_t& r3,
                                        uint32_t addr) {
    asm volatile("ldmatrix.sync.aligned.m8n8.x4.shared.b16 {%0,%1,%2,%3}, [%4];"
                 : "=r"(r0), "=r"(r1), "=r"(r2), "=r"(r3) : "r"(addr));
}

__device__ __forceinline__ void ldsm_x2(uint32_t& r0, uint32_t& r1, uint32_t addr) {
    asm volatile("ldmatrix.sync.aligned.m8n8.x2.shared.b16 {%0,%1}, [%2];"
                 : "=r"(r0), "=r"(r1) : "r"(addr));
}

__device__ __forceinline__ void mma_f16(float4& c, const uint32_t a[4], const uint32_t b[2]) {
    asm volatile(
        "mma.sync.aligned.m16n8k16.row.col.f32.f16.f16.f32 "
        "{%0,%1,%2,%3}, {%4,%5,%6,%7}, {%8,%9}, {%0,%1,%2,%3};"
        : "+f"(c.x), "+f"(c.y), "+f"(c.z), "+f"(c.w)
        : "r"(a[0]), "r"(a[1]), "r"(a[2]), "r"(a[3]), "r"(b[0]), "r"(b[1]));
}

// ---------------------------------------------------------------------------
// BK=64 buffer, stride 36 uint32 rows (conflict-free: 36r mod 32 = 4r).
// 4 k-halves per buffer. MT=4 m-tiles, NT=4 n-tiles, warp grid 2x4.
// ---------------------------------------------------------------------------
template <int MT, int NT>
__device__ __forceinline__ void mma_ldsm36(uint32_t as_base, uint32_t bs_base,
                                           float4 acc[MT][NT],
                                           int warp_m, int warp_n, int lane) {
    const uint32_t arow = (uint32_t)(warp_m * (MT * 16) + (lane & 7) + ((lane >> 3) & 1) * 8);
    const uint32_t acol = (uint32_t)((lane >> 4) * 4);
    const uint32_t a_off = as_base + (arow * 36 + acol) * 4;
    const uint32_t brow = (uint32_t)((lane & 7) + (lane >> 4) * 8);
    const uint32_t bcol = (uint32_t)(((lane >> 3) & 1) * 4);
    const uint32_t cb = (uint32_t)(warp_n * NT * 8);
    const uint32_t b_off = bs_base + ((cb + brow) * 36 + bcol) * 4;

#pragma unroll
    for (int ks = 0; ks < 4; ks++) {
        uint32_t af[MT][4];
#pragma unroll
        for (int mt = 0; mt < MT; mt++)
            ldsm_x4(af[mt][0], af[mt][1], af[mt][2], af[mt][3],
                    a_off + (uint32_t)((mt * 16 * 36 + ks * 8) * 4));

        uint32_t bf[NT][2];
#pragma unroll
        for (int p = 0; p < NT / 2; p++)
            ldsm_x4(bf[2 * p][0], bf[2 * p][1], bf[2 * p + 1][0], bf[2 * p + 1][1],
                    b_off + (uint32_t)((p * 16 * 36 + ks * 8) * 4));

#pragma unroll
        for (int mt = 0; mt < MT; mt++)
#pragma unroll
            for (int nt = 0; nt < NT; nt++) mma_f16(acc[mt][nt], af[mt], bf[nt]);
    }
}

// BK=32 buffer, stride 20 (scores + pv).
template <int MT, int NT>
__device__ __forceinline__ void mma_ldsm20(uint32_t as_base, uint32_t bs_base,
                                           float4 acc[MT][NT],
                                           int warp_m, int warp_n, int lane) {
    const uint32_t arow = (uint32_t)(warp_m * (MT * 16) + (lane & 7) + ((lane >> 3) & 1) * 8);
    const uint32_t acol = (uint32_t)((lane >> 4) * 4);
    const uint32_t a_off = as_base + (arow * 20 + acol) * 4;
    const uint32_t brow = (uint32_t)((lane & 7) + (lane >> 4) * 8);
    const uint32_t bcol = (uint32_t)(((lane >> 3) & 1) * 4);
    const uint32_t cb = (uint32_t)(warp_n * NT * 8);
    const uint32_t b_off = bs_base + ((cb + brow) * 20 + bcol) * 4;

#pragma unroll
    for (int ks = 0; ks < 2; ks++) {
        uint32_t af[MT][4];
#pragma unroll
        for (int mt = 0; mt < MT; mt++)
            ldsm_x4(af[mt][0], af[mt][1], af[mt][2], af[mt][3],
                    a_off + (uint32_t)((mt * 16 * 20 + ks * 8) * 4));

        uint32_t bf[NT][2];
#pragma unroll
        for (int p = 0; p < NT / 2; p++)
            ldsm_x4(bf[2 * p][0], bf[2 * p][1], bf[2 * p + 1][0], bf[2 * p + 1][1],
                    b_off + (uint32_t)((p * 16 * 20 + ks * 8) * 4));
        if (NT & 1) {
            const uint32_t row2 = cb + (uint32_t)((NT - 1) * 8) + (uint32_t)(lane & 7);
            const uint32_t col2 = (uint32_t)(((lane >> 3) & 1) * 4);
            ldsm_x2(bf[NT - 1][0], bf[NT - 1][1],
                    bs_base + (row2 * 20 + col2 + (uint32_t)(ks * 8)) * 4);
        }

#pragma unroll
        for (int mt = 0; mt < MT; mt++)
#pragma unroll
            for (int nt = 0; nt < NT; nt++) mma_f16(acc[mt][nt], af[mt], bf[nt]);
    }
}

// ---------------------------------------------------------------------------
// Fused fp32 -> fp16 convert of all 6 tensors. Block = 2048 elements.
// ---------------------------------------------------------------------------
#define NXBLK (MROWS * E / 2048)      // 3072
#define NWBLK (E * E / 2048)          // 288
__global__ void cvt_all(const float* __restrict__ m, const float* __restrict__ p,
                        const float* __restrict__ qw, const float* __restrict__ kw,
                        const float* __restrict__ vw, const float* __restrict__ ow) {
    int blk = blockIdx.x;
    const float* src;
    __half* dst;
    if (blk < NXBLK)                { src = m;  dst = g_Xm; }
    else if (blk < 2 * NXBLK)       { src = p;  dst = g_Xp; blk -= NXBLK; }
    else if (blk < 2 * NXBLK + NWBLK)       { src = qw; dst = g_Wq; blk -= 2 * NXBLK; }
    else if (blk < 2 * NXBLK + 2 * NWBLK)   { src = kw; dst = g_Wk; blk -= 2 * NXBLK + NWBLK; }
    else if (blk < 2 * NXBLK + 3 * NWBLK)   { src = vw; dst = g_Wv; blk -= 2 * NXBLK + 2 * NWBLK; }
    else                                    { src = ow; dst = g_Wo; blk -= 2 * NXBLK + 3 * NWBLK; }
    const int i = blk * 2048 + threadIdx.x * 8;
    const float4 a = *(const float4*)&src[i];
    const float4 b = *(const float4*)&src[i + 4];
    uint4 u;
    u.x = pack_half2(__float2half_rn(a.x), __float2half_rn(a.y));
    u.y = pack_half2(__float2half_rn(a.z), __float2half_rn(a.w));
    u.z = pack_half2(__float2half_rn(b.x), __float2half_rn(b.y));
    u.w = pack_half2(__float2half_rn(b.z), __float2half_rn(b.w));
    *(uint4*)&dst[i] = u;
}

// ---------------------------------------------------------------------------
// Linears: BK=64, 3-stage cp.async ring, stride-36 stages of 18432 B.
// ---------------------------------------------------------------------------
#define STSZ64 18432u                     // 128*36*4
#define LIN_SMEM (6 * 18432)              // 3 stages x 2 operands = 110592
#define STSZ20 10240u                     // 128*20*4 (scores)
#define SC_SMEM  (6 * 10240)

// Per-thread loader constants for BK=64: row = tid>>1, halves base = (tid&1)*32.
__device__ __forceinline__ void load_stage64(uint32_t a_dst, uint32_t b_dst,
                                             const __half* ap, const __half* bp) {
#pragma unroll
    for (int q = 0; q < 4; q++) {
        cp_async16(a_dst + q * 16, ap + q * 8);
        cp_async16(b_dst + q * 16, bp + q * 8);
    }
}

// ---------------------------------------------------------------------------
// QKV linear, single launch: grid.z selects (X, W, bias, out). out fp16 [b,h,m,d].
// ---------------------------------------------------------------------------
__launch_bounds__(256, 2)
__global__ void qkv_f16(const __half* __restrict__ Xm_, const __half* __restrict__ Xp_,
                        const __half* __restrict__ Wq_, const __half* __restrict__ Wk_,
                        const __half* __restrict__ Wv_,
                        const float* __restrict__ qb, const float* __restrict__ kb,
                        const float* __restrict__ vb,
                        __half* __restrict__ Qo, __half* __restrict__ Ko,
                        __half* __restrict__ Vo) {
    extern __shared__ uint32_t dyn[];
    const int z = blockIdx.z;
    const __half* X = (z == 0) ? Xm_ : Xp_;
    const __half* W = (z == 0) ? Wq_ : ((z == 1) ? Wk_ : Wv_);
    const float* bias = (z == 0) ? qb : ((z == 1) ? kb : vb);
    __half* out = (z == 0) ? Qo : ((z == 1) ? Ko : Vo);

    const int tid = threadIdx.x;
    const int lane = tid & 31;
    const int w = tid >> 5;
    const int warp_m = w & 1, warp_n = w >> 1;
    const int g = lane >> 2, t = lane & 3;
    const int row0 = blockIdx.y * 128, col0 = blockIdx.x * 128;

    const uint32_t base = smem_u32(dyn);
    const uint32_t as0 = base, bs0 = base + 3 * STSZ64;

    const int row_ld = tid >> 1;
    const int hb = (tid & 1) * 32;        // halves base within 64
    const uint32_t a_dst = as0 + (uint32_t)(row_ld * 36 + hb / 2) * 4;
    const uint32_t b_dst = bs0 + (uint32_t)(row_ld * 36 + hb / 2) * 4;
    const __half* a_row = X + (size_t)(row0 + row_ld) * E + hb;
    const __half* b_row = W + (size_t)(col0 + row_ld) * E + hb;

    float4 acc[4][4];
#pragma unroll
    for (int i = 0; i < 4; i++)
#pragma unroll
        for (int j = 0; j < 4; j++) acc[i][j] = make_float4(0.f, 0.f, 0.f, 0.f);

    const int KT = E / 64;   // 12
    load_stage64(a_dst, b_dst, a_row, b_row); cp_commit();
    load_stage64(a_dst + STSZ64, b_dst + STSZ64, a_row + 64, b_row + 64); cp_commit();

    for (int kt = 0; kt < KT; kt++) {
        cp_wait<1>();
        __syncthreads();
        const uint32_t slot = (uint32_t)(kt % 3);
        mma_ldsm36<4, 4>(as0 + slot * STSZ64, bs0 + slot * STSZ64, acc, warp_m, warp_n, lane);
        if (kt + 2 < KT) {
            const uint32_t st = (uint32_t)((kt + 2) % 3);
            load_stage64(a_dst + st * STSZ64, b_dst + st * STSZ64,
                         a_row + (kt + 2) * 64, b_row + (kt + 2) * 64);
        }
        cp_commit();
        __syncthreads();
    }

#pragma unroll
    for (int mt = 0; mt < 4; mt++) {
        const int r = row0 + warp_m * 64 + mt * 16 + g;
#pragma unroll
        for (int nt = 0; nt < 4; nt++) {
            const int c = col0 + warp_n * 32 + nt * 8 + 2 * t;
            const float bx = bias[c], by = bias[c + 1];
            const float v0x = acc[mt][nt].x + bx, v0y = acc[mt][nt].y + by;
            const float v1x = acc[mt][nt].z + bx, v1y = acc[mt][nt].w + by;
            const int bb_ = r >> 10, m = r & 1023;
            const int hh = c / D, d = c - hh * D;
            const size_t o0 = (((size_t)(bb_ * H + hh)) * NTOK + m) * D + d;
            const int bb2 = (r + 8) >> 10, m2 = (r + 8) & 1023;
            const size_t o1 = (((size_t)(bb2 * H + hh)) * NTOK + m2) * D + d;
            *(__half2*)&out[o0] = __floats2half2_rn(v0x, v0y);
            *(__half2*)&out[o1] = __floats2half2_rn(v1x, v1y);
        }
    }
}

// ---------------------------------------------------------------------------
// O linear: fp16 in, fp32 out row-major. BK=64, same ring.
// ---------------------------------------------------------------------------
__launch_bounds__(256, 2)
__global__ void o_linear(const __half* __restrict__ X, const __half* __restrict__ W,
                         const float* __restrict__ bias, float* __restrict__ out) {
    extern __shared__ uint32_t dyn[];

    const int tid = threadIdx.x;
    const int lane = tid & 31;
    const int w = tid >> 5;
    const int warp_m = w & 1, warp_n = w >> 1;
    const int g = lane >> 2, t = lane & 3;
    const int row0 = blockIdx.y * 128, col0 = blockIdx.x * 128;

    const uint32_t base = smem_u32(dyn);
    const uint32_t as0 = base, bs0 = base + 3 * STSZ64;

    const int row_ld = tid >> 1;
    const int hb = (tid & 1) * 32;
    const uint32_t a_dst = as0 + (uint32_t)(row_ld * 36 + hb / 2) * 4;
    const uint32_t b_dst = bs0 + (uint32_t)(row_ld * 36 + hb / 2) * 4;
    const __half* a_row = X + (size_t)(row0 + row_ld) * E + hb;
    const __half* b_row = W + (size_t)(col0 + row_ld) * E + hb;

    float4 acc[4][4];
#pragma unroll
    for (int i = 0; i < 4; i++)
#pragma unroll
        for (int j = 0; j < 4; j++) acc[i][j] = make_float4(0.f, 0.f, 0.f, 0.f);

    const int KT = E / 64;   // 12
    load_stage64(a_dst, b_dst, a_row, b_row); cp_commit();
    load_stage64(a_dst + STSZ64, b_dst + STSZ64, a_row + 64, b_row + 64); cp_commit();

    for (int kt = 0; kt < KT; kt++) {
        cp_wait<1>();
        __syncthreads();
        const uint32_t slot = (uint32_t)(kt % 3);
        mma_ldsm36<4, 4>(as0 + slot * STSZ64, bs0 + slot * STSZ64, acc, warp_m, warp_n, lane);
        if (kt + 2 < KT) {
            const uint32_t st = (uint32_t)((kt + 2) % 3);
            load_stage64(a_dst + st * STSZ64, b_dst + st * STSZ64,
                         a_row + (kt + 2) * 64, b_row + (kt + 2) * 64);
        }
        cp_commit();
        __syncthreads();
    }

#pragma unroll
    for (int mt = 0; mt < 4; mt++) {
        const int r = row0 + warp_m * 64 + mt * 16 + g;
#pragma unroll
        for (int nt = 0; nt < 4; nt++) {
            const int c = col0 + warp_n * 32 + nt * 8 + 2 * t;
            const float bx = bias[c], by = bias[c + 1];
            *(float2*)&out[(size_t)r * E + c] =
                make_float2(acc[mt][nt].x + bx, acc[mt][nt].y + by);
            *(float2*)&out[(size_t)(r + 8) * E + c] =
                make_float2(acc[mt][nt].z + bx, acc[mt][nt].w + by);
        }
    }
}

// ---------------------------------------------------------------------------
// Scores: per z: S = scale * Q @ K^T. BK=32, 3 stages all prefetched (KT=3).
// ---------------------------------------------------------------------------
__launch_bounds__(256, 2)
__global__ void scores_f16(const __half* __restrict__ Q,
                           const __half* __restrict__ K,
                           __half* __restrict__ S, float scale) {
    extern __shared__ uint32_t dyn[];

    const int z = blockIdx.z;
    const __half* Qz = Q + (size_t)z * NTOK * D;
    const __half* Kz = K + (size_t)z * NTOK * D;
    __half* Sz = S + (size_t)z * NTOK * NTOK;

    const int tid = threadIdx.x;
    const int lane = tid & 31;
    const int w = tid >> 5;
    const int warp_m = w & 1, warp_n = w >> 1;
    const int g = lane >> 2, t = lane & 3;
    const int row0 = blockIdx.y * 128, col0 = blockIdx.x * 128;

    const uint32_t base = smem_u32(dyn);
    const uint32_t as0 = base, bs0 = base + 3 * STSZ20;

    const int row_ld = tid >> 1;
    const int c0 = (tid & 1) * 8;
    const uint32_t a_dst = as0 + (uint32_t)(row_ld * 20 + c0) * 4;
    const uint32_t b_dst = bs0 + (uint32_t)(row_ld * 20 + c0) * 4;
    const __half* a_row = Qz + (size_t)(row0 + row_ld) * D;
    const __half* b_row = Kz + (size_t)(col0 + row_ld) * D;

    float4 acc[4][4];
#pragma unroll
    for (int i = 0; i < 4; i++)
#pragma unroll
        for (int j = 0; j < 4; j++) acc[i][j] = make_float4(0.f, 0.f, 0.f, 0.f);

#pragma unroll
    for (int s = 0; s < 3; s++) {
        const __half* ap = a_row + s * 32 + c0 * 2;
        const __half* bp = b_row + s * 32 + c0 * 2;
        cp_async16(a_dst + s * STSZ20, ap);
        cp_async16(a_dst + s * STSZ20 + 16, ap + 8);
        cp_async16(b_dst + s * STSZ20, bp);
        cp_async16(b_dst + s * STSZ20 + 16, bp + 8);
        cp_commit();
    }
    cp_wait<2>();
    __syncthreads();

#pragma unroll
    for (int kt = 0; kt < 3; kt++) {
        mma_ldsm20<4, 4>(as0 + kt * STSZ20, bs0 + kt * STSZ20, acc, warp_m, warp_n, lane);
        if (kt == 0) { cp_wait<1>(); __syncthreads(); }
        else if (kt == 1) { cp_wait<0>(); __syncthreads(); }
    }

#pragma unroll
    for (int mt = 0; mt < 4; mt++) {
        const int m = row0 + warp_m * 64 + mt * 16 + g;
#pragma unroll
        for (int nt = 0; nt < 4; nt++) {
            const int p = col0 + warp_n * 32 + nt * 8 + 2 * t;
            *(__half2*)&Sz[(size_t)m * NTOK + p] =
                __floats2half2_rn(acc[mt][nt].x * scale, acc[mt][nt].y * scale);
            *(__half2*)&Sz[(size_t)(m + 8) * NTOK + p] =
                __floats2half2_rn(acc[mt][nt].z * scale, acc[mt][nt].w * scale);
        }
    }
}

// ---------------------------------------------------------------------------
// Fused softmax (in place, fp16) + head-average (fp32 out).
// smem holds fp16 P rows (16 KB) — half the traffic of the fp32 version.
// ---------------------------------------------------------------------------
__launch_bounds__(256)
__global__ void softmax_avg(__half* __restrict__ S, float* __restrict__ avg_out) {
    __shared__ uint4 sm[8][128];          // 8 rows x 1024 halves
    const int bm = blockIdx.x;
    const int b = bm >> 10, m = bm & 1023;
    const int w = threadIdx.x >> 5, lane = threadIdx.x & 31;

    uint4* row = (uint4*)(S + (((size_t)(b * H + w)) * NTOK + m) * NTOK);
    float x[32];
    float mx = -INFINITY;
#pragma unroll
    for (int j = 0; j < 4; j++) {
        const uint4 u = row[lane + j * 32];
        const __half2* hp = (const __half2*)&u;
#pragma unroll
        for (int q = 0; q < 4; q++) {
            const float2 f = __half22float2(hp[q]);
            x[j * 8 + q * 2 + 0] = f.x;
            x[j * 8 + q * 2 + 1] = f.y;
            mx = fmaxf(mx, fmaxf(f.x, f.y));
        }
    }
#pragma unroll
    for (int o = 16; o > 0; o >>= 1) mx = fmaxf(mx, __shfl_xor_sync(0xffffffffu, mx, o));

    float sum = 0.f;
#pragma unroll
    for (int i = 0; i < 32; i++) {
        x[i] = __expf(x[i] - mx);
        sum += x[i];
    }
#pragma unroll
    for (int o = 16; o > 0; o >>= 1) sum += __shfl_xor_sync(0xffffffffu, sum, o);
    const float inv = 1.f / sum;

#pragma unroll
    for (int j = 0; j < 4; j++) {
        uint4 u;
        __half2* hp = (__half2*)&u;
#pragma unroll
        for (int q = 0; q < 4; q++)
            hp[q] = __floats2half2_rn(x[j * 8 + q * 2] * inv, x[j * 8 + q * 2 + 1] * inv);
        row[lane + j * 32] = u;
        sm[w][lane + j * 32] = u;
    }
    __syncthreads();

    // avg: thread tt handles positions 4tt..4tt+3 (two __half2 per head).
    const int tt = threadIdx.x;
    float a0 = 0.f, a1 = 0.f, a2 = 0.f, a3 = 0.f;
    const uint32_t* smw = (const uint32_t*)&sm[0][0];
#pragma unroll
    for (int h = 0; h < 8; h++) {
        const uint32_t u0 = smw[h * 512 + tt * 2 + 0];
        const uint32_t u1 = smw[h * 512 + tt * 2 + 1];
        const float2 f0 = __half22float2(*(const __half2*)&u0);
        const float2 f1 = __half22float2(*(const __half2*)&u1);
        a0 += f0.x; a1 += f0.y; a2 += f1.x; a3 += f1.y;
    }
    ((float4*)(avg_out + (size_t)bm * NTOK))[tt] =
        make_float4(a0 * 0.125f, a1 * 0.125f, a2 * 0.125f, a3 * 0.125f);
}

// ---------------------------------------------------------------------------
// PV: per z: C[1024,96] = P[1024,1024] @ V[1024,96], fp16 in/out.
// 256 threads, BK=32, double-buffered register prefetch (static smem).
// ---------------------------------------------------------------------------
__launch_bounds__(256)
__global__ void pv_f16(const __half* __restrict__ S,
                       const __half* __restrict__ V,
                       __half* __restrict__ A) {
    __shared__ uint32_t As[2][128][20];
    __shared__ uint32_t Bs[2][96][20];

    const int z = blockIdx.z;
    const int b = z >> 3, h = z & 7;
    const __half* Pz = S + (size_t)z * NTOK * NTOK;
    const __half* Vz = V + (size_t)z * NTOK * D;

    const int tid = threadIdx.x;
    const int lane = tid & 31;
    const int w = tid >> 5;
    const int warp_m = w & 1, warp_n = w >> 1;
    const int g = lane >> 2, t = lane & 3;
    const int row0 = blockIdx.y * 128;

    const int arow0 = tid >> 2;
    const int lq = (tid & 3) * 8;
    const int c0 = lq >> 1;

    const uint32_t as0 = smem_u32(&As[0][0][0]);
    const uint32_t bs0 = smem_u32(&Bs[0][0][0]);
    const uint32_t absz = 128 * 20 * 4;
    const uint32_t bbsz = 96 * 20 * 4;

    float4 acc[4][3];
#pragma unroll
    for (int i = 0; i < 4; i++)
#pragma unroll
        for (int j = 0; j < 3; j++) acc[i][j] = make_float4(0.f, 0.f, 0.f, 0.f);

#pragma unroll
    for (int s = 0; s < 2; s++) {
        const int r = arow0 + s * 64;
        const uint4 a = *(const uint4*)&Pz[(size_t)(row0 + r) * NTOK + lq];
        As[0][r][c0 + 0] = a.x; As[0][r][c0 + 1] = a.y; As[0][r][c0 + 2] = a.z; As[0][r][c0 + 3] = a.w;
    }
#pragma unroll
    for (int s = 0; s < 6; s++) {
        const int idx = tid + s * 256;
        const int d = idx % D;
        const int j = idx / D;
        Bs[0][d][j] = pack_half2(Vz[(size_t)(2 * j) * D + d], Vz[(size_t)(2 * j + 1) * D + d]);
    }
    __syncthreads();

    int buf = 0;
    const int KT = NTOK / 32;  // 32
    for (int kt = 0; kt < KT; kt++) {
        uint4 pa[2];
        uint32_t pvv[6];
        if (kt + 1 < KT) {
            const int k0 = (kt + 1) * 32;
#pragma unroll
            for (int s = 0; s < 2; s++) {
                const int r = arow0 + s * 64;
                pa[s] = *(const uint4*)&Pz[(size_t)(row0 + r) * NTOK + k0 + lq];
            }
#pragma unroll
            for (int s = 0; s < 6; s++) {
                const int idx = tid + s * 256;
                const int d = idx % D;
                const int j = idx / D;
                pvv[s] = pack_half2(Vz[(size_t)(k0 + 2 * j) * D + d],
                                    Vz[(size_t)(k0 + 2 * j + 1) * D + d]);
            }
        }
        mma_ldsm20<4, 3>(as0 + buf * absz, bs0 + buf * bbsz, acc, warp_m, warp_n, lane);
        if (kt + 1 < KT) {
            const int nb = buf ^ 1;
#pragma unroll
            for (int s = 0; s < 2; s++) {
                const int r = arow0 + s * 64;
                As[nb][r][c0 + 0] = pa[s].x; As[nb][r][c0 + 1] = pa[s].y;
                As[nb][r][c0 + 2] = pa[s].z; As[nb][r][c0 + 3] = pa[s].w;
            }
#pragma unroll
            for (int s = 0; s < 6; s++) {
                const int idx = tid + s * 256;
                const int d = idx % D;
                const int j = idx / D;
                Bs[nb][d][j] = pvv[s];
            }
            buf = nb;
        }
        __syncthreads();
    }

#pragma unroll
    for (int mt = 0; mt < 4; mt++) {
        const int m = row0 + warp_m * 64 + mt * 16 + g;
#pragma unroll
        for (int nt = 0; nt < 3; nt++) {
            const int d = warp_n * 24 + nt * 8 + 2 * t;
            *(__half2*)&A[((size_t)b * NTOK + m) * E + h * D + d] =
                __floats2half2_rn(acc[mt][nt].x, acc[mt][nt].y);
            *(__half2*)&A[((size_t)b * NTOK + m + 8) * E + h * D + d] =
                __floats2half2_rn(acc[mt][nt].z, acc[mt][nt].w);
        }
    }
}

// ---------------------------------------------------------------------------
extern "C" void kernel_launch(void* const* d_in, const int* in_sizes, int n_in,
                              void* d_out, int out_size) {
    const float* mammo = (const float*)d_in[0];
    const float* patho = (const float*)d_in[1];
    const float* q_w = (const float*)d_in[2];
    const float* q_b = (const float*)d_in[3];
    const float* k_w = (const float*)d_in[4];
    const float* k_b = (const float*)d_in[5];
    const float* v_w = (const float*)d_in[6];
    const float* v_b = (const float*)d_in[7];
    const float* o_w = (const float*)d_in[8];
    const float* o_b = (const float*)d_in[9];

    float* out_attended = (float*)d_out;
    float* out_attn_avg = (float*)d_out + (size_t)B * NTOK * E;

    __half *Xm, *Xp, *Wq, *Wk, *Wv, *Wo, *Qp, *Kp, *Vp, *Sp, *Ap;
    cudaGetSymbolAddress((void**)&Xm, g_Xm);
    cudaGetSymbolAddress((void**)&Xp, g_Xp);
    cudaGetSymbolAddress((void**)&Wq, g_Wq);
    cudaGetSymbolAddress((void**)&Wk, g_Wk);
    cudaGetSymbolAddress((void**)&Wv, g_Wv);
    cudaGetSymbolAddress((void**)&Wo, g_Wo);
    cudaGetSymbolAddress((void**)&Qp, g_Q);
    cudaGetSymbolAddress((void**)&Kp, g_K);
    cudaGetSymbolAddress((void**)&Vp, g_V);
    cudaGetSymbolAddress((void**)&Sp, g_S);
    cudaGetSymbolAddress((void**)&Ap, g_A);

    cudaFuncSetAttribute(qkv_f16, cudaFuncAttributeMaxDynamicSharedMemorySize, LIN_SMEM);
    cudaFuncSetAttribute(o_linear, cudaFuncAttributeMaxDynamicSharedMemorySize, LIN_SMEM);
    cudaFuncSetAttribute(scores_f16, cudaFuncAttributeMaxDynamicSharedMemorySize, SC_SMEM);

    cvt_all<<<2 * NXBLK + 4 * NWBLK, 256>>>(mammo, patho, q_w, k_w, v_w, o_w);

    qkv_f16<<<dim3(E / 128, MROWS / 128, 3), 256, LIN_SMEM>>>(
        Xm, Xp, Wq, Wk, Wv, q_b, k_b, v_b, Qp, Kp, Vp);

    const float scale = 1.0f / sqrtf((float)D);
    scores_f16<<<dim3(NTOK / 128, NTOK / 128, BHM), 256, SC_SMEM>>>(Qp, Kp, Sp, scale);

    softmax_avg<<<B * NTOK, 256>>>(Sp, out_attn_avg);

    pv_f16<<<dim3(1, NTOK / 128, BHM), 256>>>(Sp, Vp, Ap);

    o_linear<<<dim3(E / 128, MROWS / 128), 256, LIN_SMEM>>>(Ap, Wo, o_b, out_attended);
}

// round 14
// speedup vs baseline: 1.0749x; 1.0749x over previous
#include <cuda_runtime.h>
#include <cuda_fp16.h>
#include <math.h>
#include <stdint.h>

// Problem constants
#define B 8
#define NTOK 1024
#define E 768
#define H 8
#define D 96
#define BHM (B * H)
#define MROWS (B * NTOK)

// ---------------- device scratch (no allocations allowed) ----------------
__device__ __half g_Xm[MROWS * E];
__device__ __half g_Xp[MROWS * E];
__device__ __half g_Wq[E * E];
__device__ __half g_Wk[E * E];
__device__ __half g_Wv[E * E];
__device__ __half g_Wo[E * E];
__device__ __half g_Q[B * H * NTOK * D];
__device__ __half g_K[B * H * NTOK * D];
__device__ __half g_V[B * H * NTOK * D];
__device__ __half g_S[(size_t)BHM * NTOK * NTOK];
__device__ __half g_A[B * NTOK * E];

// ---------------------------------------------------------------------------
__device__ __forceinline__ uint32_t pack_half2(__half lo, __half hi) {
    __half2 h = __halves2half2(lo, hi);
    return *reinterpret_cast<uint32_t*>(&h);
}

__device__ __forceinline__ uint32_t smem_u32(const void* p) {
    uint32_t a;
    asm("{ .reg .u64 t; cvta.to.shared.u64 t, %1; cvt.u32.u64 %0, t; }"
        : "=r"(a) : "l"(p));
    return a;
}

__device__ __forceinline__ void cp_async16(uint32_t smem_addr, const void* gptr) {
    asm volatile("cp.async.cg.shared.global [%0], [%1], 16;"
                 :: "r"(smem_addr), "l"(gptr));
}
__device__ __forceinline__ void cp_commit() {
    asm volatile("cp.async.commit_group;");
}
template <int N>
__device__ __forceinline__ void cp_wait() {
    asm volatile("cp.async.wait_group %0;" :: "n"(N));
}

__device__ __forceinline__ void ldsm_x4(uint32_t& r0, uint32_t& r1, uint32_t& r2, uint32_t& r3,
                                        uint32_t addr) {
    asm volatile("ldmatrix.sync.aligned.m8n8.x4.shared.b16 {%0,%1,%2,%3}, [%4];"
                 : "=r"(r0), "=r"(r1), "=r"(r2), "=r"(r3) : "r"(addr));
}

__device__ __forceinline__ void ldsm_x2(uint32_t& r0, uint32_t& r1, uint32_t addr) {
    asm volatile("ldmatrix.sync.aligned.m8n8.x2.shared.b16 {%0,%1}, [%2];"
                 : "=r"(r0), "=r"(r1) : "r"(addr));
}

__device__ __forceinline__ void mma_f16(float4& c, const uint32_t a[4], const uint32_t b[2]) {
    asm volatile(
        "mma.sync.aligned.m16n8k16.row.col.f32.f16.f16.f32 "
        "{%0,%1,%2,%3}, {%4,%5,%6,%7}, {%8,%9}, {%0,%1,%2,%3};"
        : "+f"(c.x), "+f"(c.y), "+f"(c.z), "+f"(c.w)
        : "r"(a[0]), "r"(a[1]), "r"(a[2]), "r"(a[3]), "r"(b[0]), "r"(b[1]));
}

// ---------------------------------------------------------------------------
// BK=32 buffer, stride 20 uint32 rows (conflict-free for LDSM).
// MT m-tiles of 16 rows, NT n-tiles of 8. Two k-halves per buffer.
// ---------------------------------------------------------------------------
template <int MT, int NT>
__device__ __forceinline__ void mma_ldsm20(uint32_t as_base, uint32_t bs_base,
                                           float4 acc[MT][NT],
                                           int warp_m, int warp_n, int lane) {
    const uint32_t arow = (uint32_t)(warp_m * (MT * 16) + (lane & 7) + ((lane >> 3) & 1) * 8);
    const uint32_t acol = (uint32_t)((lane >> 4) * 4);
    const uint32_t a_off = as_base + (arow * 20 + acol) * 4;
    const uint32_t brow = (uint32_t)((lane & 7) + (lane >> 4) * 8);
    const uint32_t bcol = (uint32_t)(((lane >> 3) & 1) * 4);
    const uint32_t cb = (uint32_t)(warp_n * NT * 8);
    const uint32_t b_off = bs_base + ((cb + brow) * 20 + bcol) * 4;

#pragma unroll
    for (int ks = 0; ks < 2; ks++) {
        uint32_t af[MT][4];
#pragma unroll
        for (int mt = 0; mt < MT; mt++)
            ldsm_x4(af[mt][0], af[mt][1], af[mt][2], af[mt][3],
                    a_off + (uint32_t)((mt * 16 * 20 + ks * 8) * 4));

        uint32_t bf[NT][2];
#pragma unroll
        for (int p = 0; p < NT / 2; p++)
            ldsm_x4(bf[2 * p][0], bf[2 * p][1], bf[2 * p + 1][0], bf[2 * p + 1][1],
                    b_off + (uint32_t)((p * 16 * 20 + ks * 8) * 4));
        if (NT & 1) {
            const uint32_t row2 = cb + (uint32_t)((NT - 1) * 8) + (uint32_t)(lane & 7);
            const uint32_t col2 = (uint32_t)(((lane >> 3) & 1) * 4);
            ldsm_x2(bf[NT - 1][0], bf[NT - 1][1],
                    bs_base + (row2 * 20 + col2 + (uint32_t)(ks * 8)) * 4);
        }

#pragma unroll
        for (int mt = 0; mt < MT; mt++)
#pragma unroll
            for (int nt = 0; nt < NT; nt++) mma_f16(acc[mt][nt], af[mt], bf[nt]);
    }
}

// ---------------------------------------------------------------------------
// Fused fp32 -> fp16 convert of all 6 tensors. Block = 2048 elements.
// ---------------------------------------------------------------------------
#define NXBLK (MROWS * E / 2048)      // 3072
#define NWBLK (E * E / 2048)          // 288
__global__ void cvt_all(const float* __restrict__ m, const float* __restrict__ p,
                        const float* __restrict__ qw, const float* __restrict__ kw,
                        const float* __restrict__ vw, const float* __restrict__ ow) {
    int blk = blockIdx.x;
    const float* src;
    __half* dst;
    if (blk < NXBLK)                { src = m;  dst = g_Xm; }
    else if (blk < 2 * NXBLK)       { src = p;  dst = g_Xp; blk -= NXBLK; }
    else if (blk < 2 * NXBLK + NWBLK)       { src = qw; dst = g_Wq; blk -= 2 * NXBLK; }
    else if (blk < 2 * NXBLK + 2 * NWBLK)   { src = kw; dst = g_Wk; blk -= 2 * NXBLK + NWBLK; }
    else if (blk < 2 * NXBLK + 3 * NWBLK)   { src = vw; dst = g_Wv; blk -= 2 * NXBLK + 2 * NWBLK; }
    else                                    { src = ow; dst = g_Wo; blk -= 2 * NXBLK + 3 * NWBLK; }
    const int i = blk * 2048 + threadIdx.x * 8;
    const float4 a = *(const float4*)&src[i];
    const float4 b = *(const float4*)&src[i + 4];
    uint4 u;
    u.x = pack_half2(__float2half_rn(a.x), __float2half_rn(a.y));
    u.y = pack_half2(__float2half_rn(a.z), __float2half_rn(a.w));
    u.z = pack_half2(__float2half_rn(b.x), __float2half_rn(b.y));
    u.w = pack_half2(__float2half_rn(b.z), __float2half_rn(b.w));
    *(uint4*)&dst[i] = u;
}

// ---------------------------------------------------------------------------
// Shared BK=32, 4-stage cp.async GEMM mainloop (128x128 CTA tile, 256 thr).
// ---------------------------------------------------------------------------
#define STSZ 10240u                       // 128*20*4 bytes per operand stage
#define LIN_SMEM (8 * 10240)              // 4 stages x 2 operands
#define SC_SMEM  (6 * 10240)              // 3 stages x 2 operands

// ---------------------------------------------------------------------------
// QKV linear, single launch: grid.z selects (X, W, bias, out). out fp16 [b,h,m,d].
// ---------------------------------------------------------------------------
__launch_bounds__(256, 2)
__global__ void qkv_f16(const __half* __restrict__ Xm_, const __half* __restrict__ Xp_,
                        const __half* __restrict__ Wq_, const __half* __restrict__ Wk_,
                        const __half* __restrict__ Wv_,
                        const float* __restrict__ qb, const float* __restrict__ kb,
                        const float* __restrict__ vb,
                        __half* __restrict__ Qo, __half* __restrict__ Ko,
                        __half* __restrict__ Vo) {
    extern __shared__ uint32_t dyn[];
    const int z = blockIdx.z;
    const __half* X = (z == 0) ? Xm_ : Xp_;
    const __half* W = (z == 0) ? Wq_ : ((z == 1) ? Wk_ : Wv_);
    const float* bias = (z == 0) ? qb : ((z == 1) ? kb : vb);
    __half* out = (z == 0) ? Qo : ((z == 1) ? Ko : Vo);

    const int tid = threadIdx.x;
    const int lane = tid & 31;
    const int w = tid >> 5;
    const int warp_m = w & 1, warp_n = w >> 1;
    const int g = lane >> 2, t = lane & 3;
    const int row0 = blockIdx.y * 128, col0 = blockIdx.x * 128;

    const uint32_t base = smem_u32(dyn);
    const uint32_t as0 = base, bs0 = base + 4 * STSZ;

    const int row_ld = tid >> 1;          // 0..127
    const int c0 = (tid & 1) * 8;         // uint32 col base: 0 or 8
    const uint32_t a_dst = as0 + (uint32_t)(row_ld * 20 + c0) * 4;
    const uint32_t b_dst = bs0 + (uint32_t)(row_ld * 20 + c0) * 4;
    const __half* a_row = X + (size_t)(row0 + row_ld) * E;
    const __half* b_row = W + (size_t)(col0 + row_ld) * E;

    float4 acc[4][4];
#pragma unroll
    for (int i = 0; i < 4; i++)
#pragma unroll
        for (int j = 0; j < 4; j++) acc[i][j] = make_float4(0.f, 0.f, 0.f, 0.f);

    const int KT = E / 32;   // 24
#pragma unroll
    for (int s = 0; s < 3; s++) {
        const __half* ap = a_row + s * 32 + c0 * 2;
        const __half* bp = b_row + s * 32 + c0 * 2;
        cp_async16(a_dst + s * STSZ, ap);
        cp_async16(a_dst + s * STSZ + 16, ap + 8);
        cp_async16(b_dst + s * STSZ, bp);
        cp_async16(b_dst + s * STSZ + 16, bp + 8);
        cp_commit();
    }
    cp_wait<2>();
    __syncthreads();

    for (int kt = 0; kt < KT; kt++) {
        const uint32_t slot = (uint32_t)(kt & 3);
        mma_ldsm20<4, 4>(as0 + slot * STSZ, bs0 + slot * STSZ, acc, warp_m, warp_n, lane);
        if (kt + 3 < KT) {
            const uint32_t st = (uint32_t)((kt + 3) & 3);
            const __half* ap = a_row + (kt + 3) * 32 + c0 * 2;
            const __half* bp = b_row + (kt + 3) * 32 + c0 * 2;
            cp_async16(a_dst + st * STSZ, ap);
            cp_async16(a_dst + st * STSZ + 16, ap + 8);
            cp_async16(b_dst + st * STSZ, bp);
            cp_async16(b_dst + st * STSZ + 16, bp + 8);
        }
        cp_commit();
        cp_wait<2>();
        __syncthreads();
    }

#pragma unroll
    for (int mt = 0; mt < 4; mt++) {
        const int r = row0 + warp_m * 64 + mt * 16 + g;
#pragma unroll
        for (int nt = 0; nt < 4; nt++) {
            const int c = col0 + warp_n * 32 + nt * 8 + 2 * t;
            const float bx = bias[c], by = bias[c + 1];
            const float v0x = acc[mt][nt].x + bx, v0y = acc[mt][nt].y + by;
            const float v1x = acc[mt][nt].z + bx, v1y = acc[mt][nt].w + by;
            const int bb_ = r >> 10, m = r & 1023;
            const int hh = c / D, d = c - hh * D;
            const size_t o0 = (((size_t)(bb_ * H + hh)) * NTOK + m) * D + d;
            const int bb2 = (r + 8) >> 10, m2 = (r + 8) & 1023;
            const size_t o1 = (((size_t)(bb2 * H + hh)) * NTOK + m2) * D + d;
            *(__half2*)&out[o0] = __floats2half2_rn(v0x, v0y);
            *(__half2*)&out[o1] = __floats2half2_rn(v1x, v1y);
        }
    }
}

// ---------------------------------------------------------------------------
// O linear: fp16 in, fp32 out row-major. Same BK=32 mainloop.
// ---------------------------------------------------------------------------
__launch_bounds__(256, 2)
__global__ void o_linear(const __half* __restrict__ X, const __half* __restrict__ W,
                         const float* __restrict__ bias, float* __restrict__ out) {
    extern __shared__ uint32_t dyn[];

    const int tid = threadIdx.x;
    const int lane = tid & 31;
    const int w = tid >> 5;
    const int warp_m = w & 1, warp_n = w >> 1;
    const int g = lane >> 2, t = lane & 3;
    const int row0 = blockIdx.y * 128, col0 = blockIdx.x * 128;

    const uint32_t base = smem_u32(dyn);
    const uint32_t as0 = base, bs0 = base + 4 * STSZ;

    const int row_ld = tid >> 1;
    const int c0 = (tid & 1) * 8;
    const uint32_t a_dst = as0 + (uint32_t)(row_ld * 20 + c0) * 4;
    const uint32_t b_dst = bs0 + (uint32_t)(row_ld * 20 + c0) * 4;
    const __half* a_row = X + (size_t)(row0 + row_ld) * E;
    const __half* b_row = W + (size_t)(col0 + row_ld) * E;

    float4 acc[4][4];
#pragma unroll
    for (int i = 0; i < 4; i++)
#pragma unroll
        for (int j = 0; j < 4; j++) acc[i][j] = make_float4(0.f, 0.f, 0.f, 0.f);

    const int KT = E / 32;   // 24
#pragma unroll
    for (int s = 0; s < 3; s++) {
        const __half* ap = a_row + s * 32 + c0 * 2;
        const __half* bp = b_row + s * 32 + c0 * 2;
        cp_async16(a_dst + s * STSZ, ap);
        cp_async16(a_dst + s * STSZ + 16, ap + 8);
        cp_async16(b_dst + s * STSZ, bp);
        cp_async16(b_dst + s * STSZ + 16, bp + 8);
        cp_commit();
    }
    cp_wait<2>();
    __syncthreads();

    for (int kt = 0; kt < KT; kt++) {
        const uint32_t slot = (uint32_t)(kt & 3);
        mma_ldsm20<4, 4>(as0 + slot * STSZ, bs0 + slot * STSZ, acc, warp_m, warp_n, lane);
        if (kt + 3 < KT) {
            const uint32_t st = (uint32_t)((kt + 3) & 3);
            const __half* ap = a_row + (kt + 3) * 32 + c0 * 2;
            const __half* bp = b_row + (kt + 3) * 32 + c0 * 2;
            cp_async16(a_dst + st * STSZ, ap);
            cp_async16(a_dst + st * STSZ + 16, ap + 8);
            cp_async16(b_dst + st * STSZ, bp);
            cp_async16(b_dst + st * STSZ + 16, bp + 8);
        }
        cp_commit();
        cp_wait<2>();
        __syncthreads();
    }

#pragma unroll
    for (int mt = 0; mt < 4; mt++) {
        const int r = row0 + warp_m * 64 + mt * 16 + g;
#pragma unroll
        for (int nt = 0; nt < 4; nt++) {
            const int c = col0 + warp_n * 32 + nt * 8 + 2 * t;
            const float bx = bias[c], by = bias[c + 1];
            *(float2*)&out[(size_t)r * E + c] =
                make_float2(acc[mt][nt].x + bx, acc[mt][nt].y + by);
            *(float2*)&out[(size_t)(r + 8) * E + c] =
                make_float2(acc[mt][nt].z + bx, acc[mt][nt].w + by);
        }
    }
}

// ---------------------------------------------------------------------------
// Scores: per z: S = scale * Q @ K^T. BK=32, 3 stages all prefetched (KT=3).
// ---------------------------------------------------------------------------
__launch_bounds__(256, 2)
__global__ void scores_f16(const __half* __restrict__ Q,
                           const __half* __restrict__ K,
                           __half* __restrict__ S, float scale) {
    extern __shared__ uint32_t dyn[];

    const int z = blockIdx.z;
    const __half* Qz = Q + (size_t)z * NTOK * D;
    const __half* Kz = K + (size_t)z * NTOK * D;
    __half* Sz = S + (size_t)z * NTOK * NTOK;

    const int tid = threadIdx.x;
    const int lane = tid & 31;
    const int w = tid >> 5;
    const int warp_m = w & 1, warp_n = w >> 1;
    const int g = lane >> 2, t = lane & 3;
    const int row0 = blockIdx.y * 128, col0 = blockIdx.x * 128;

    const uint32_t base = smem_u32(dyn);
    const uint32_t as0 = base, bs0 = base + 3 * STSZ;

    const int row_ld = tid >> 1;
    const int c0 = (tid & 1) * 8;
    const uint32_t a_dst = as0 + (uint32_t)(row_ld * 20 + c0) * 4;
    const uint32_t b_dst = bs0 + (uint32_t)(row_ld * 20 + c0) * 4;
    const __half* a_row = Qz + (size_t)(row0 + row_ld) * D;
    const __half* b_row = Kz + (size_t)(col0 + row_ld) * D;

    float4 acc[4][4];
#pragma unroll
    for (int i = 0; i < 4; i++)
#pragma unroll
        for (int j = 0; j < 4; j++) acc[i][j] = make_float4(0.f, 0.f, 0.f, 0.f);

#pragma unroll
    for (int s = 0; s < 3; s++) {
        const __half* ap = a_row + s * 32 + c0 * 2;
        const __half* bp = b_row + s * 32 + c0 * 2;
        cp_async16(a_dst + s * STSZ, ap);
        cp_async16(a_dst + s * STSZ + 16, ap + 8);
        cp_async16(b_dst + s * STSZ, bp);
        cp_async16(b_dst + s * STSZ + 16, bp + 8);
        cp_commit();
    }
    cp_wait<2>();
    __syncthreads();

#pragma unroll
    for (int kt = 0; kt < 3; kt++) {
        mma_ldsm20<4, 4>(as0 + kt * STSZ, bs0 + kt * STSZ, acc, warp_m, warp_n, lane);
        if (kt == 0) { cp_wait<1>(); __syncthreads(); }
        else if (kt == 1) { cp_wait<0>(); __syncthreads(); }
    }

#pragma unroll
    for (int mt = 0; mt < 4; mt++) {
        const int m = row0 + warp_m * 64 + mt * 16 + g;
#pragma unroll
        for (int nt = 0; nt < 4; nt++) {
            const int p = col0 + warp_n * 32 + nt * 8 + 2 * t;
            *(__half2*)&Sz[(size_t)m * NTOK + p] =
                __floats2half2_rn(acc[mt][nt].x * scale, acc[mt][nt].y * scale);
            *(__half2*)&Sz[(size_t)(m + 8) * NTOK + p] =
                __floats2half2_rn(acc[mt][nt].z * scale, acc[mt][nt].w * scale);
        }
    }
}

// ---------------------------------------------------------------------------
// Fused softmax (in place, fp16) + head-average (fp32 out).
// smem holds fp16 P rows (16 KB).
// ---------------------------------------------------------------------------
__launch_bounds__(256)
__global__ void softmax_avg(__half* __restrict__ S, float* __restrict__ avg_out) {
    __shared__ uint4 sm[8][128];          // 8 rows x 1024 halves
    const int bm = blockIdx.x;
    const int b = bm >> 10, m = bm & 1023;
    const int w = threadIdx.x >> 5, lane = threadIdx.x & 31;

    uint4* row = (uint4*)(S + (((size_t)(b * H + w)) * NTOK + m) * NTOK);
    float x[32];
    float mx = -INFINITY;
#pragma unroll
    for (int j = 0; j < 4; j++) {
        const uint4 u = row[lane + j * 32];
        const __half2* hp = (const __half2*)&u;
#pragma unroll
        for (int q = 0; q < 4; q++) {
            const float2 f = __half22float2(hp[q]);
            x[j * 8 + q * 2 + 0] = f.x;
            x[j * 8 + q * 2 + 1] = f.y;
            mx = fmaxf(mx, fmaxf(f.x, f.y));
        }
    }
#pragma unroll
    for (int o = 16; o > 0; o >>= 1) mx = fmaxf(mx, __shfl_xor_sync(0xffffffffu, mx, o));

    float sum = 0.f;
#pragma unroll
    for (int i = 0; i < 32; i++) {
        x[i] = __expf(x[i] - mx);
        sum += x[i];
    }
#pragma unroll
    for (int o = 16; o > 0; o >>= 1) sum += __shfl_xor_sync(0xffffffffu, sum, o);
    const float inv = 1.f / sum;

#pragma unroll
    for (int j = 0; j < 4; j++) {
        uint4 u;
        __half2* hp = (__half2*)&u;
#pragma unroll
        for (int q = 0; q < 4; q++)
            hp[q] = __floats2half2_rn(x[j * 8 + q * 2] * inv, x[j * 8 + q * 2 + 1] * inv);
        row[lane + j * 32] = u;
        sm[w][lane + j * 32] = u;
    }
    __syncthreads();

    const int tt = threadIdx.x;
    float a0 = 0.f, a1 = 0.f, a2 = 0.f, a3 = 0.f;
    const uint32_t* smw = (const uint32_t*)&sm[0][0];
#pragma unroll
    for (int h = 0; h < 8; h++) {
        const uint32_t u0 = smw[h * 512 + tt * 2 + 0];
        const uint32_t u1 = smw[h * 512 + tt * 2 + 1];
        const float2 f0 = __half22float2(*(const __half2*)&u0);
        const float2 f1 = __half22float2(*(const __half2*)&u1);
        a0 += f0.x; a1 += f0.y; a2 += f1.x; a3 += f1.y;
    }
    ((float4*)(avg_out + (size_t)bm * NTOK))[tt] =
        make_float4(a0 * 0.125f, a1 * 0.125f, a2 * 0.125f, a3 * 0.125f);
}

// ---------------------------------------------------------------------------
// PV: per z: C[1024,96] = P[1024,1024] @ V[1024,96], fp16 in/out.
// 256 threads, BK=32, double-buffered register prefetch (static smem).
// ---------------------------------------------------------------------------
__launch_bounds__(256)
__global__ void pv_f16(const __half* __restrict__ S,
                       const __half* __restrict__ V,
                       __half* __restrict__ A) {
    __shared__ uint32_t As[2][128][20];
    __shared__ uint32_t Bs[2][96][20];

    const int z = blockIdx.z;
    const int b = z >> 3, h = z & 7;
    const __half* Pz = S + (size_t)z * NTOK * NTOK;
    const __half* Vz = V + (size_t)z * NTOK * D;

    const int tid = threadIdx.x;
    const int lane = tid & 31;
    const int w = tid >> 5;
    const int warp_m = w & 1, warp_n = w >> 1;
    const int g = lane >> 2, t = lane & 3;
    const int row0 = blockIdx.y * 128;

    const int arow0 = tid >> 2;
    const int lq = (tid & 3) * 8;
    const int c0 = lq >> 1;

    const uint32_t as0 = smem_u32(&As[0][0][0]);
    const uint32_t bs0 = smem_u32(&Bs[0][0][0]);
    const uint32_t absz = 128 * 20 * 4;
    const uint32_t bbsz = 96 * 20 * 4;

    float4 acc[4][3];
#pragma unroll
    for (int i = 0; i < 4; i++)
#pragma unroll
        for (int j = 0; j < 3; j++) acc[i][j] = make_float4(0.f, 0.f, 0.f, 0.f);

#pragma unroll
    for (int s = 0; s < 2; s++) {
        const int r = arow0 + s * 64;
        const uint4 a = *(const uint4*)&Pz[(size_t)(row0 + r) * NTOK + lq];
        As[0][r][c0 + 0] = a.x; As[0][r][c0 + 1] = a.y; As[0][r][c0 + 2] = a.z; As[0][r][c0 + 3] = a.w;
    }
#pragma unroll
    for (int s = 0; s < 6; s++) {
        const int idx = tid + s * 256;
        const int d = idx % D;
        const int j = idx / D;
        Bs[0][d][j] = pack_half2(Vz[(size_t)(2 * j) * D + d], Vz[(size_t)(2 * j + 1) * D + d]);
    }
    __syncthreads();

    int buf = 0;
    const int KT = NTOK / 32;  // 32
    for (int kt = 0; kt < KT; kt++) {
        uint4 pa[2];
        uint32_t pvv[6];
        if (kt + 1 < KT) {
            const int k0 = (kt + 1) * 32;
#pragma unroll
            for (int s = 0; s < 2; s++) {
                const int r = arow0 + s * 64;
                pa[s] = *(const uint4*)&Pz[(size_t)(row0 + r) * NTOK + k0 + lq];
            }
#pragma unroll
            for (int s = 0; s < 6; s++) {
                const int idx = tid + s * 256;
                const int d = idx % D;
                const int j = idx / D;
                pvv[s] = pack_half2(Vz[(size_t)(k0 + 2 * j) * D + d],
                                    Vz[(size_t)(k0 + 2 * j + 1) * D + d]);
            }
        }
        mma_ldsm20<4, 3>(as0 + buf * absz, bs0 + buf * bbsz, acc, warp_m, warp_n, lane);
        if (kt + 1 < KT) {
            const int nb = buf ^ 1;
#pragma unroll
            for (int s = 0; s < 2; s++) {
                const int r = arow0 + s * 64;
                As[nb][r][c0 + 0] = pa[s].x; As[nb][r][c0 + 1] = pa[s].y;
                As[nb][r][c0 + 2] = pa[s].z; As[nb][r][c0 + 3] = pa[s].w;
            }
#pragma unroll
            for (int s = 0; s < 6; s++) {
                const int idx = tid + s * 256;
                const int d = idx % D;
                const int j = idx / D;
                Bs[nb][d][j] = pvv[s];
            }
            buf = nb;
        }
        __syncthreads();
    }

#pragma unroll
    for (int mt = 0; mt < 4; mt++) {
        const int m = row0 + warp_m * 64 + mt * 16 + g;
#pragma unroll
        for (int nt = 0; nt < 3; nt++) {
            const int d = warp_n * 24 + nt * 8 + 2 * t;
            *(__half2*)&A[((size_t)b * NTOK + m) * E + h * D + d] =
                __floats2half2_rn(acc[mt][nt].x, acc[mt][nt].y);
            *(__half2*)&A[((size_t)b * NTOK + m + 8) * E + h * D + d] =
                __floats2half2_rn(acc[mt][nt].z, acc[mt][nt].w);
        }
    }
}

// ---------------------------------------------------------------------------
extern "C" void kernel_launch(void* const* d_in, const int* in_sizes, int n_in,
                              void* d_out, int out_size) {
    const float* mammo = (const float*)d_in[0];
    const float* patho = (const float*)d_in[1];
    const float* q_w = (const float*)d_in[2];
    const float* q_b = (const float*)d_in[3];
    const float* k_w = (const float*)d_in[4];
    const float* k_b = (const float*)d_in[5];
    const float* v_w = (const float*)d_in[6];
    const float* v_b = (const float*)d_in[7];
    const float* o_w = (const float*)d_in[8];
    const float* o_b = (const float*)d_in[9];

    float* out_attended = (float*)d_out;
    float* out_attn_avg = (float*)d_out + (size_t)B * NTOK * E;

    __half *Xm, *Xp, *Wq, *Wk, *Wv, *Wo, *Qp, *Kp, *Vp, *Sp, *Ap;
    cudaGetSymbolAddress((void**)&Xm, g_Xm);
    cudaGetSymbolAddress((void**)&Xp, g_Xp);
    cudaGetSymbolAddress((void**)&Wq, g_Wq);
    cudaGetSymbolAddress((void**)&Wk, g_Wk);
    cudaGetSymbolAddress((void**)&Wv, g_Wv);
    cudaGetSymbolAddress((void**)&Wo, g_Wo);
    cudaGetSymbolAddress((void**)&Qp, g_Q);
    cudaGetSymbolAddress((void**)&Kp, g_K);
    cudaGetSymbolAddress((void**)&Vp, g_V);
    cudaGetSymbolAddress((void**)&Sp, g_S);
    cudaGetSymbolAddress((void**)&Ap, g_A);

    cudaFuncSetAttribute(qkv_f16, cudaFuncAttributeMaxDynamicSharedMemorySize, LIN_SMEM);
    cudaFuncSetAttribute(o_linear, cudaFuncAttributeMaxDynamicSharedMemorySize, LIN_SMEM);
    cudaFuncSetAttribute(scores_f16, cudaFuncAttributeMaxDynamicSharedMemorySize, SC_SMEM);

    cvt_all<<<2 * NXBLK + 4 * NWBLK, 256>>>(mammo, patho, q_w, k_w, v_w, o_w);

    qkv_f16<<<dim3(E / 128, MROWS / 128, 3), 256, LIN_SMEM>>>(
        Xm, Xp, Wq, Wk, Wv, q_b, k_b, v_b, Qp, Kp, Vp);

    const float scale = 1.0f / sqrtf((float)D);
    scores_f16<<<dim3(NTOK / 128, NTOK / 128, BHM), 256, SC_SMEM>>>(Qp, Kp, Sp, scale);

    softmax_avg<<<B * NTOK, 256>>>(Sp, out_attn_avg);

    pv_f16<<<dim3(1, NTOK / 128, BHM), 256>>>(Sp, Vp, Ap);

    o_linear<<<dim3(E / 128, MROWS / 128), 256, LIN_SMEM>>>(Ap, Wo, o_b, out_attended);
}